// round 1
// baseline (speedup 1.0000x reference)
#include <cuda_runtime.h>
#include <cstdint>

#define B_    8
#define CIN   64
#define H_    128
#define W_    128
#define COUT  128
#define HO    131
#define WO    131

// Scratch (device globals are the sanctioned workaround for no-alloc rule)
__device__ __align__(16) float g_y [B_ * COUT * H_ * W_];   // conv3x3 out, 67 MB
__device__ __align__(16) float g_xh[B_ * COUT * HO * WO];   // depthwise+silu out, 70 MB

// ---------------- f32x2 packed-FP32 helpers (Blackwell full-rate FP32) ----------------
__device__ __forceinline__ unsigned long long pack2(float lo, float hi) {
    unsigned long long r;
    asm("mov.b64 %0, {%1, %2};" : "=l"(r) : "f"(lo), "f"(hi));
    return r;
}
__device__ __forceinline__ void unpack2(unsigned long long v, float& lo, float& hi) {
    asm("mov.b64 {%0, %1}, %2;" : "=f"(lo), "=f"(hi) : "l"(v));
}
__device__ __forceinline__ unsigned long long fma2(unsigned long long a, unsigned long long b,
                                                   unsigned long long c) {
    unsigned long long d;
    asm("fma.rn.f32x2 %0, %1, %2, %3;" : "=l"(d) : "l"(a), "l"(b), "l"(c));
    return d;
}

// ---------------- Stage 1: 3x3 conv, 64 -> 128 channels (W_in rows 128..255), pad 1 ----
// Block: 4 rows x 16 cols spatial tile, all 128 out channels. 256 threads.
// Thread: 8 oc x 4 cols (2 f32x2 pairs). K streamed in ic-chunks of 4.
__global__ __launch_bounds__(256, 2)
void conv3x3_kernel(const float* __restrict__ x, const float* __restrict__ W_in) {
    __shared__ float Xs[4][6][18];                  // 4 ic x (4+2) rows x (16+2) cols halo
    __shared__ unsigned long long Ws2[36 * 144];    // (ic*9+kk) x swizzled 128 oc, (w,w) pairs

    const int tid = threadIdx.x;
    const int e   = tid & 15;          // oc octet 0..15  -> oc = e*8 .. e*8+7
    const int q   = tid >> 4;          // 0..15
    const int r   = q & 3;             // tile row
    const int cg4 = (q >> 2) * 4;      // tile col base (4 cols per thread)

    const int gj0 = blockIdx.x * 16;
    const int gi0 = blockIdx.y * 4;
    const int b   = blockIdx.z;

    unsigned long long acc[8][2];
#pragma unroll
    for (int j = 0; j < 8; ++j) { acc[j][0] = 0ull; acc[j][1] = 0ull; }

    const float* xb = x + (size_t)b * CIN * H_ * W_;

    for (int ic0 = 0; ic0 < CIN; ic0 += 4) {
        // ---- load input tile 4 x 6 x 18 = 432 floats (zero halo at borders)
        for (int idx = tid; idx < 432; idx += 256) {
            int ic  = idx / 108;
            int rem = idx - ic * 108;
            int rr  = rem / 18;
            int cc  = rem - rr * 18;
            int gr  = gi0 - 1 + rr;
            int gc  = gj0 - 1 + cc;
            float v = 0.f;
            if ((unsigned)gr < H_ && (unsigned)gc < W_)
                v = xb[((size_t)(ic0 + ic) * H_ + gr) * W_ + gc];
            Xs[ic][rr][cc] = v;
        }
        // ---- load weights: 128 oc x 36 (=4 ic x 9 taps), coalesced-by-oc-row,
        //      stored duplicated (w,w) with x9 swizzle so 16-lane oc-octet reads are
        //      bank-conflict-free.
        for (int idx = tid; idx < 4608; idx += 256) {
            int oc = idx / 36;
            int t  = idx - oc * 36;                         // = ic_local*9 + kk
            float w = W_in[(size_t)(128 + oc) * (CIN * 9) + ic0 * 9 + t];
            int eo = oc >> 3, jo = oc & 7;
            Ws2[t * 144 + eo * 9 + jo] = pack2(w, w);
        }
        __syncthreads();

#pragma unroll
        for (int ic = 0; ic < 4; ++ic) {
#pragma unroll
            for (int ky = 0; ky < 3; ++ky) {
                const float* xr = &Xs[ic][r + ky][cg4];
                float x0 = xr[0], x1 = xr[1], x2 = xr[2],
                      x3 = xr[3], x4 = xr[4], x5 = xr[5];
                unsigned long long pa[3] = { pack2(x0, x1), pack2(x1, x2), pack2(x2, x3) };
                unsigned long long pb[3] = { pack2(x2, x3), pack2(x3, x4), pack2(x4, x5) };
#pragma unroll
                for (int kx = 0; kx < 3; ++kx) {
                    const unsigned long long* wp = &Ws2[(ic * 9 + ky * 3 + kx) * 144 + e * 9];
#pragma unroll
                    for (int j = 0; j < 8; ++j) {
                        unsigned long long w = wp[j];
                        acc[j][0] = fma2(w, pa[kx], acc[j][0]);
                        acc[j][1] = fma2(w, pb[kx], acc[j][1]);
                    }
                }
            }
        }
        __syncthreads();
    }

    float* yb = g_y + (size_t)b * COUT * H_ * W_;
#pragma unroll
    for (int j = 0; j < 8; ++j) {
        float o0, o1, o2, o3;
        unpack2(acc[j][0], o0, o1);
        unpack2(acc[j][1], o2, o3);
        *(float4*)(yb + ((size_t)(e * 8 + j) * H_ + (gi0 + r)) * W_ + gj0 + cg4)
            = make_float4(o0, o1, o2, o3);
    }
}

// ---------------- Stage 2: depthwise 4x4 conv, pad (3,3) -> 131x131, + bias + silu ------
__global__ __launch_bounds__(256)
void dwconv_kernel(const float* __restrict__ Wc, const float* __restrict__ bc) {
    __shared__ float Xs[35][35];
    __shared__ float ws[16];
    __shared__ float bias_s;

    const int tid  = threadIdx.x;
    const int tile = blockIdx.x;       // 0..24
    const int c    = blockIdx.y;       // 0..127
    const int b    = blockIdx.z;
    const int i0   = (tile / 5) * 32;
    const int j0   = (tile % 5) * 32;

    const float* yb = g_y + ((size_t)b * COUT + c) * H_ * W_;

    for (int idx = tid; idx < 35 * 35; idx += 256) {
        int rr = idx / 35, cc = idx - (idx / 35) * 35;
        int gr = i0 - 3 + rr, gc = j0 - 3 + cc;
        float v = 0.f;
        if ((unsigned)gr < H_ && (unsigned)gc < W_) v = yb[gr * W_ + gc];
        Xs[rr][cc] = v;
    }
    if (tid < 16)  ws[tid] = Wc[c * 16 + tid];
    if (tid == 16) bias_s  = bc[c];
    __syncthreads();

    float* ob = g_xh + ((size_t)b * COUT + c) * HO * WO;
#pragma unroll
    for (int k = 0; k < 4; ++k) {
        int p  = tid + k * 256;
        int oy = p >> 5, ox = p & 31;
        int gi = i0 + oy, gj = j0 + ox;
        if (gi < HO && gj < WO) {
            float a = bias_s;
#pragma unroll
            for (int ky = 0; ky < 4; ++ky)
#pragma unroll
                for (int kx = 0; kx < 4; ++kx)
                    a += Xs[oy + ky][ox + kx] * ws[ky * 4 + kx];
            ob[gi * WO + gj] = a / (1.f + __expf(-a));   // silu
        }
    }
}

// ---------------- Stage 3: flat-reshape head matmul: out[g,e] = xh_flat[g,:] . W_out[e,:]
#define GG 549152            // 8 * 128*131*131 / 32 groups of 32
__global__ __launch_bounds__(256, 4)
void headmm_kernel(const float* __restrict__ W_out, float* __restrict__ out) {
    __shared__ float Vs[2048];          // 64 groups per chunk
    const int tid = threadIdx.x;
    const int e   = tid & 31;
    const int wp  = tid >> 5;           // 0..7

    float wrow[32];
#pragma unroll
    for (int d = 0; d < 32; ++d) wrow[d] = W_out[e * 32 + d];

    const int nchunks = (GG + 63) / 64;                  // 8581
    for (int ch = blockIdx.x; ch < nchunks; ch += gridDim.x) {
        size_t base  = (size_t)ch * 2048;
        int    nelem = min(2048, (int)((size_t)GG * 32 - base));
        int    nvec  = nelem >> 2;
        for (int idx = tid; idx < nvec; idx += 256)
            *(float4*)&Vs[idx * 4] = *(const float4*)(g_xh + base + (size_t)idx * 4);
        __syncthreads();
        int ng = nelem >> 5;
#pragma unroll
        for (int k = 0; k < 8; ++k) {
            int gl = wp + k * 8;
            if (gl < ng) {
                const float* v = &Vs[gl * 32];
                float a = 0.f;
#pragma unroll
                for (int d = 0; d < 32; ++d) a += wrow[d] * v[d];
                out[base + (size_t)gl * 32 + e] = a;
            }
        }
        __syncthreads();
    }
}

// ---------------- launch ----------------
extern "C" void kernel_launch(void* const* d_in, const int* in_sizes, int n_in,
                              void* d_out, int out_size) {
    const float* x      = (const float*)d_in[0];
    const float* W_in   = (const float*)d_in[1];
    const float* W_conv = (const float*)d_in[2];
    const float* b_conv = (const float*)d_in[3];
    // d_in[4..6] (dt_bias, A_log, D) are dead w.r.t. the returned output
    const float* W_out  = (const float*)d_in[7];
    float* out = (float*)d_out;

    conv3x3_kernel<<<dim3(8, 32, 8), 256>>>(x, W_in);
    dwconv_kernel <<<dim3(25, 128, 8), 256>>>(W_conv, b_conv);
    headmm_kernel <<<8581, 256>>>(W_out, out);
}

// round 5
// speedup vs baseline: 2.5050x; 2.5050x over previous
#include <cuda_runtime.h>
#include <cuda_bf16.h>
#include <cstdint>

#define B_    8
#define CIN   64
#define H_    128
#define W_    128
#define COUT  128
#define HO    131
#define WO    131

// ---------------- device scratch ----------------
__device__ __align__(16) float          g_y [B_ * COUT * H_ * W_];
__device__ __align__(16) float          g_xh[B_ * COUT * HO * WO];
__device__ __align__(16) __nv_bfloat16  g_Xh[B_ * H_ * W_ * CIN];   // NHWC hi
__device__ __align__(16) __nv_bfloat16  g_Xl[B_ * H_ * W_ * CIN];   // NHWC lo
__device__ __align__(16) __nv_bfloat16  g_Wh[9 * COUT * CIN];       // [tap][oc][ic] hi
__device__ __align__(16) __nv_bfloat16  g_Wl[9 * COUT * CIN];       // [tap][oc][ic] lo

// ---------------- helpers ----------------
__device__ __forceinline__ uint32_t smem_u32(const void* p) {
    uint32_t a;
    asm("{ .reg .u64 t; cvta.to.shared.u64 t, %1; cvt.u32.u64 %0, t; }" : "=r"(a) : "l"(p));
    return a;
}
__device__ __forceinline__ void cp16(uint32_t dst, const void* src) {
    asm volatile("cp.async.cg.shared.global [%0], [%1], 16;" :: "r"(dst), "l"(src));
}
#define CP_COMMIT() asm volatile("cp.async.commit_group;" ::: "memory")
#define CP_WAIT1()  asm volatile("cp.async.wait_group 1;" ::: "memory")

__device__ __forceinline__ void ldmx4(uint32_t addr, uint32_t& r0, uint32_t& r1,
                                      uint32_t& r2, uint32_t& r3) {
    asm volatile("ldmatrix.sync.aligned.m8n8.x4.shared.b16 {%0,%1,%2,%3}, [%4];"
                 : "=r"(r0), "=r"(r1), "=r"(r2), "=r"(r3) : "r"(addr));
}
__device__ __forceinline__ void mma16816(float* c, const uint32_t* a, uint32_t b0, uint32_t b1) {
    asm volatile(
        "mma.sync.aligned.m16n8k16.row.col.f32.bf16.bf16.f32 "
        "{%0,%1,%2,%3}, {%4,%5,%6,%7}, {%8,%9}, {%0,%1,%2,%3};"
        : "+f"(c[0]), "+f"(c[1]), "+f"(c[2]), "+f"(c[3])
        : "r"(a[0]), "r"(a[1]), "r"(a[2]), "r"(a[3]), "r"(b0), "r"(b1));
}

// ---------------- SMEM layout (bytes) ----------------
// X buffers: 2 x { hi[132 slots x 144B], lo[132 x 144B] }  slot = px+1, px in -1..130
// W buffers: 2 x { hi[128 x 144B], lo[128 x 144B] }
#define XBUF(b)   ((b) * 38016)
#define XLOFF     19008
#define WBUF(b)   (76032 + (b) * 36864)
#define WLOFF     18432
#define SM_TOTAL  149760

// ---------------- prep kernels ----------------
__global__ void prep_w_kernel(const float* __restrict__ W_in) {
    int tap = blockIdx.x;      // 0..8
    int oc  = threadIdx.x;     // 0..127
    for (int ic = 0; ic < CIN; ++ic) {
        float v = W_in[(size_t)((128 + oc) * CIN + ic) * 9 + tap];
        __nv_bfloat16 h = __float2bfloat16(v);
        __nv_bfloat16 l = __float2bfloat16(v - __bfloat162float(h));
        g_Wh[(tap * COUT + oc) * CIN + ic] = h;
        g_Wl[(tap * COUT + oc) * CIN + ic] = l;
    }
}

__global__ __launch_bounds__(256) void prep_x_kernel(const float* __restrict__ x) {
    __shared__ float s[W_ * (CIN + 1)];
    int y = blockIdx.x, b = blockIdx.y, tid = threadIdx.x;
    for (int k = 0; k < 32; ++k) {
        int idx = tid + k * 256;
        int ic = idx >> 7, xx = idx & 127;
        s[xx * (CIN + 1) + ic] = x[((size_t)(b * CIN + ic) * H_ + y) * W_ + xx];
    }
    __syncthreads();
    size_t obase = ((size_t)(b * H_ + y) * W_) * CIN;
    for (int k = 0; k < 32; ++k) {
        int idx = tid + k * 256;
        int p = idx >> 6, ic = idx & 63;
        float f = s[p * (CIN + 1) + ic];
        __nv_bfloat16 h = __float2bfloat16(f);
        __nv_bfloat16 l = __float2bfloat16(f - __bfloat162float(h));
        g_Xh[obase + (size_t)p * CIN + ic] = h;
        g_Xl[obase + (size_t)p * CIN + ic] = l;
    }
}

// ---------------- Stage 1: implicit-GEMM conv3x3 via mma.sync ----------------
// CTA = one (b, y): out[128 oc][128 px]. K = 9 taps x 64 ic, 3 bf16 terms.
__device__ __forceinline__ void issue_xrow(uint32_t sb_x, char* sm, int xoff,
                                           int b, int row, int tid) {
    if ((unsigned)row < (unsigned)H_) {
        const char* srch = (const char*)g_Xh + ((size_t)(b * H_ + row) * W_) * CIN * 2;
        const char* srcl = (const char*)g_Xl + ((size_t)(b * H_ + row) * W_) * CIN * 2;
#pragma unroll
        for (int i = 0; i < 8; ++i) {
            int e = tid + i * 256;                  // 0..2047
            int half = e >> 10;                     // 0: hi, 1: lo
            int r    = (e >> 3) & 127;              // px 0..127 -> slot r+1
            int c    = e & 7;
            uint32_t dst = sb_x + (half ? XLOFF : 0) + (uint32_t)(r + 1) * 144 + c * 16;
            const char* s = (half ? srcl : srch) + (size_t)r * 128 + c * 16;
            cp16(dst, s);
        }
    } else {
        // zero slots 1..128, both halves: 2*128*36 = 9216 words over 256 threads
        for (int i = 0; i < 36; ++i) {
            int e = tid + i * 256;
            int half = e >= 4608;
            int idx  = half ? e - 4608 : e;
            int r    = idx / 36, c = idx - r * 36;
            *(uint32_t*)(sm + xoff + (half ? XLOFF : 0) + (r + 1) * 144 + c * 4) = 0u;
        }
    }
}

__device__ __forceinline__ void issue_w(uint32_t sb_w, int tap, int tid) {
#pragma unroll
    for (int i = 0; i < 8; ++i) {
        int e = tid + i * 256;
        int half = e >> 10;
        int oc   = (e >> 3) & 127;
        int c    = e & 7;
        uint32_t dst = sb_w + (half ? WLOFF : 0) + (uint32_t)oc * 144 + c * 16;
        const char* s = (const char*)(half ? g_Wl : g_Wh)
                        + ((size_t)tap * COUT + oc) * 128 + c * 16;
        cp16(dst, s);
    }
}

__global__ __launch_bounds__(256, 1)
void conv3x3_mma_kernel() {
    extern __shared__ char sm[];
    const uint32_t sbase = smem_u32(sm);
    const int tid = threadIdx.x;
    const int b   = blockIdx.x >> 7;
    const int y   = blockIdx.x & 127;

    const int wid = tid >> 5, l = tid & 31;
    const int mrow0 = (wid >> 1) * 32;      // warp M origin (oc)
    const int ncol0 = (wid & 1) * 64;       // warp N origin (px)
    const uint32_t frag_off = (uint32_t)(l & 15) * 144 + (uint32_t)(l >> 4) * 16;

    // zero halo slots 0 and 129 for BOTH buffers and BOTH halves:
    // 2 buf * 2 half * 2 slot * 36 words = 288 words, strided over 256 threads.
    for (int e = tid; e < 288; e += 256) {
        int buf  = e / 144;
        int rem  = e - buf * 144;
        int half = rem / 72;
        int rem2 = rem - half * 72;
        int slot = (rem2 >= 36) ? 129 : 0;
        int c    = rem2 % 36;
        *(uint32_t*)(sm + XBUF(buf) + (half ? XLOFF : 0) + slot * 144 + c * 4) = 0u;
    }

    float acc[2][8][4];
#pragma unroll
    for (int mt = 0; mt < 2; ++mt)
#pragma unroll
        for (int nt = 0; nt < 8; ++nt)
#pragma unroll
            for (int j = 0; j < 4; ++j) acc[mt][nt][j] = 0.f;

    // prologue: g0 = {Xrow(y-1)->Xb0, W0->Wb0}, g1 = {Xrow(y)->Xb1, W1->Wb1}
    issue_xrow(sbase + XBUF(0), sm, XBUF(0), b, y - 1, tid);
    issue_w(sbase + WBUF(0), 0, tid);
    CP_COMMIT();
    issue_xrow(sbase + XBUF(1), sm, XBUF(1), b, y, tid);
    issue_w(sbase + WBUF(1), 1, tid);
    CP_COMMIT();

    for (int t = 0; t < 9; ++t) {
        const int ky = (t >= 6) ? 2 : (t >= 3 ? 1 : 0);
        const int kx = t - 3 * ky;
        CP_WAIT1();
        __syncthreads();

        const uint32_t xb = sbase + XBUF(ky & 1);
        const uint32_t wb = sbase + WBUF(t & 1);
        // 3 terms: (Wh,Xh), (Wh,Xl), (Wl,Xh)
        const uint32_t aoffs[3] = { wb, wb, wb + WLOFF };
        const uint32_t boffs[3] = { xb + (uint32_t)kx * 144,
                                    xb + XLOFF + (uint32_t)kx * 144,
                                    xb + (uint32_t)kx * 144 };
#pragma unroll
        for (int term = 0; term < 3; ++term) {
            const uint32_t aB = aoffs[term] + (uint32_t)mrow0 * 144 + frag_off;
            const uint32_t bB = boffs[term] + (uint32_t)ncol0 * 144 + frag_off;
#pragma unroll
            for (int kk = 0; kk < 4; ++kk) {
                uint32_t a[8];
                ldmx4(aB + kk * 32,              a[0], a[1], a[2], a[3]);
                ldmx4(aB + 16 * 144 + kk * 32,   a[4], a[5], a[6], a[7]);
                uint32_t bf[8][2];
#pragma unroll
                for (int nb = 0; nb < 4; ++nb) {
                    uint32_t r0, r1, r2, r3;
                    ldmx4(bB + (uint32_t)nb * 16 * 144 + kk * 32, r0, r1, r2, r3);
                    bf[nb * 2 + 0][0] = r0; bf[nb * 2 + 0][1] = r2;
                    bf[nb * 2 + 1][0] = r1; bf[nb * 2 + 1][1] = r3;
                }
#pragma unroll
                for (int mt = 0; mt < 2; ++mt)
#pragma unroll
                    for (int nt = 0; nt < 8; ++nt)
                        mma16816(acc[mt][nt], a + mt * 4, bf[nt][0], bf[nt][1]);
            }
        }
        __syncthreads();
        if (t < 8) {
            if (t + 2 <= 8) issue_w(sbase + WBUF(t & 1), t + 2, tid);
            if (t == 3)     issue_xrow(sbase + XBUF(0), sm, XBUF(0), b, y + 1, tid);
            CP_COMMIT();
        }
    }

    // epilogue: C[m=oc][n=px] -> g_y[b][oc][y][px]
    float* yb = g_y + (size_t)b * COUT * H_ * W_;
#pragma unroll
    for (int mt = 0; mt < 2; ++mt) {
#pragma unroll
        for (int nt = 0; nt < 8; ++nt) {
            int r   = mrow0 + mt * 16 + (l >> 2);
            int col = ncol0 + nt * 8 + (l & 3) * 2;
            *(float2*)&yb[((size_t)r * H_ + y) * W_ + col]
                = make_float2(acc[mt][nt][0], acc[mt][nt][1]);
            *(float2*)&yb[((size_t)(r + 8) * H_ + y) * W_ + col]
                = make_float2(acc[mt][nt][2], acc[mt][nt][3]);
        }
    }
}

// ---------------- Stage 2: depthwise 4x4 + bias + silu ----------------
__global__ __launch_bounds__(256)
void dwconv_kernel(const float* __restrict__ Wc, const float* __restrict__ bc) {
    __shared__ float Xs[35][35];
    __shared__ float ws[16];
    __shared__ float bias_s;

    const int tid  = threadIdx.x;
    const int tile = blockIdx.x;
    const int c    = blockIdx.y;
    const int b    = blockIdx.z;
    const int i0   = (tile / 5) * 32;
    const int j0   = (tile % 5) * 32;

    const float* yb = g_y + ((size_t)b * COUT + c) * H_ * W_;

    for (int idx = tid; idx < 35 * 35; idx += 256) {
        int rr = idx / 35, cc = idx - (idx / 35) * 35;
        int gr = i0 - 3 + rr, gc = j0 - 3 + cc;
        float v = 0.f;
        if ((unsigned)gr < H_ && (unsigned)gc < W_) v = yb[gr * W_ + gc];
        Xs[rr][cc] = v;
    }
    if (tid < 16)  ws[tid] = Wc[c * 16 + tid];
    if (tid == 16) bias_s  = bc[c];
    __syncthreads();

    float* ob = g_xh + ((size_t)b * COUT + c) * HO * WO;
#pragma unroll
    for (int k = 0; k < 4; ++k) {
        int p  = tid + k * 256;
        int oy = p >> 5, ox = p & 31;
        int gi = i0 + oy, gj = j0 + ox;
        if (gi < HO && gj < WO) {
            float a = bias_s;
#pragma unroll
            for (int ky = 0; ky < 4; ++ky)
#pragma unroll
                for (int kx = 0; kx < 4; ++kx)
                    a += Xs[oy + ky][ox + kx] * ws[ky * 4 + kx];
            ob[gi * WO + gj] = a / (1.f + __expf(-a));
        }
    }
}

// ---------------- Stage 3: head matmul ----------------
#define GG 549152
__global__ __launch_bounds__(256, 4)
void headmm_kernel(const float* __restrict__ W_out, float* __restrict__ out) {
    __shared__ float Vs[2048];
    const int tid = threadIdx.x;
    const int e   = tid & 31;
    const int wp  = tid >> 5;

    float wrow[32];
#pragma unroll
    for (int d = 0; d < 32; ++d) wrow[d] = W_out[e * 32 + d];

    const int nchunks = (GG + 63) / 64;
    for (int ch = blockIdx.x; ch < nchunks; ch += gridDim.x) {
        size_t base  = (size_t)ch * 2048;
        int    nelem = min(2048, (int)((size_t)GG * 32 - base));
        int    nvec  = nelem >> 2;
        for (int idx = tid; idx < nvec; idx += 256)
            *(float4*)&Vs[idx * 4] = *(const float4*)(g_xh + base + (size_t)idx * 4);
        __syncthreads();
        int ng = nelem >> 5;
#pragma unroll
        for (int k = 0; k < 8; ++k) {
            int gl = wp + k * 8;
            if (gl < ng) {
                const float* v = &Vs[gl * 32];
                float a = 0.f;
#pragma unroll
                for (int d = 0; d < 32; ++d) a += wrow[d] * v[d];
                out[base + (size_t)gl * 32 + e] = a;
            }
        }
        __syncthreads();
    }
}

// ---------------- launch ----------------
extern "C" void kernel_launch(void* const* d_in, const int* in_sizes, int n_in,
                              void* d_out, int out_size) {
    const float* x      = (const float*)d_in[0];
    const float* W_in   = (const float*)d_in[1];
    const float* W_conv = (const float*)d_in[2];
    const float* b_conv = (const float*)d_in[3];
    const float* W_out  = (const float*)d_in[7];
    float* out = (float*)d_out;

    cudaFuncSetAttribute(conv3x3_mma_kernel,
                         cudaFuncAttributeMaxDynamicSharedMemorySize, SM_TOTAL);

    prep_w_kernel<<<9, 128>>>(W_in);
    prep_x_kernel<<<dim3(H_, B_), 256>>>(x);
    conv3x3_mma_kernel<<<B_ * H_, 256, SM_TOTAL>>>();
    dwconv_kernel<<<dim3(25, 128, 8), 256>>>(W_conv, b_conv);
    headmm_kernel<<<8581, 256>>>(W_out, out);
}

// round 6
// speedup vs baseline: 2.9405x; 1.1739x over previous
#include <cuda_runtime.h>
#include <cuda_fp16.h>
#include <cstdint>

#define B_    8
#define CIN   64
#define H_    128
#define W_    128
#define COUT  128
#define HO    131
#define WO    131

// ---------------- device scratch ----------------
__device__ __align__(16) float   g_y [B_ * COUT * H_ * W_];
__device__ __align__(16) float   g_xh[B_ * COUT * HO * WO];
__device__ __align__(16) __half  g_Xh[B_ * H_ * W_ * CIN];   // NHWC fp16 hi
__device__ __align__(16) __half  g_Xl[B_ * H_ * W_ * CIN];   // NHWC fp16 lo (x - hi)
__device__ __align__(16) __half  g_Wh[9 * COUT * CIN];       // [tap][oc][ic] fp16

// ---------------- helpers ----------------
__device__ __forceinline__ uint32_t smem_u32(const void* p) {
    uint32_t a;
    asm("{ .reg .u64 t; cvta.to.shared.u64 t, %1; cvt.u32.u64 %0, t; }" : "=r"(a) : "l"(p));
    return a;
}
__device__ __forceinline__ void cp16(uint32_t dst, const void* src) {
    asm volatile("cp.async.cg.shared.global [%0], [%1], 16;" :: "r"(dst), "l"(src));
}
#define CP_COMMIT() asm volatile("cp.async.commit_group;" ::: "memory")
#define CP_WAIT1()  asm volatile("cp.async.wait_group 1;" ::: "memory")

__device__ __forceinline__ void ldmx4(uint32_t addr, uint32_t& r0, uint32_t& r1,
                                      uint32_t& r2, uint32_t& r3) {
    asm volatile("ldmatrix.sync.aligned.m8n8.x4.shared.b16 {%0,%1,%2,%3}, [%4];"
                 : "=r"(r0), "=r"(r1), "=r"(r2), "=r"(r3) : "r"(addr));
}
__device__ __forceinline__ void mma16816(float* c, const uint32_t* a, uint32_t b0, uint32_t b1) {
    asm volatile(
        "mma.sync.aligned.m16n8k16.row.col.f32.f16.f16.f32 "
        "{%0,%1,%2,%3}, {%4,%5,%6,%7}, {%8,%9}, {%0,%1,%2,%3};"
        : "+f"(c[0]), "+f"(c[1]), "+f"(c[2]), "+f"(c[3])
        : "r"(a[0]), "r"(a[1]), "r"(a[2]), "r"(a[3]), "r"(b0), "r"(b1));
}

// ---------------- SMEM layout (bytes) ----------------
// X buffers: 2 x { hi[132 slots x 144B], lo[132 x 144B] }  slot = px+1
// W buffers: 2 x hi[128 x 144B]
#define XBUF(b)   ((b) * 38016)
#define XLOFF     19008
#define WBUF(b)   (76032 + (b) * 18432)
#define SM_TOTAL  112896

// ---------------- prep kernels ----------------
__global__ void prep_w_kernel(const float* __restrict__ W_in) {
    int tap = blockIdx.x;      // 0..8
    int oc  = threadIdx.x;     // 0..127
    for (int ic = 0; ic < CIN; ++ic) {
        float v = W_in[(size_t)((128 + oc) * CIN + ic) * 9 + tap];
        g_Wh[(tap * COUT + oc) * CIN + ic] = __float2half(v);
    }
}

__global__ __launch_bounds__(256) void prep_x_kernel(const float* __restrict__ x) {
    __shared__ float s[W_ * (CIN + 1)];
    int y = blockIdx.x, b = blockIdx.y, tid = threadIdx.x;
    for (int k = 0; k < 32; ++k) {
        int idx = tid + k * 256;
        int ic = idx >> 7, xx = idx & 127;
        s[xx * (CIN + 1) + ic] = x[((size_t)(b * CIN + ic) * H_ + y) * W_ + xx];
    }
    __syncthreads();
    size_t obase = ((size_t)(b * H_ + y) * W_) * CIN;
    for (int k = 0; k < 32; ++k) {
        int idx = tid + k * 256;
        int p = idx >> 6, ic = idx & 63;
        float f = s[p * (CIN + 1) + ic];
        __half h = __float2half(f);
        __half l = __float2half(f - __half2float(h));
        g_Xh[obase + (size_t)p * CIN + ic] = h;
        g_Xl[obase + (size_t)p * CIN + ic] = l;
    }
}

// ---------------- Stage 1: implicit-GEMM conv3x3, fp16 2-term ----------------
__device__ __forceinline__ void issue_xrow(uint32_t sb_x, char* sm, int xoff,
                                           int b, int row, int tid) {
    if ((unsigned)row < (unsigned)H_) {
        const char* srch = (const char*)g_Xh + ((size_t)(b * H_ + row) * W_) * CIN * 2;
        const char* srcl = (const char*)g_Xl + ((size_t)(b * H_ + row) * W_) * CIN * 2;
#pragma unroll
        for (int i = 0; i < 8; ++i) {
            int e = tid + i * 256;                  // 0..2047
            int half = e >> 10;
            int r    = (e >> 3) & 127;
            int c    = e & 7;
            uint32_t dst = sb_x + (half ? XLOFF : 0) + (uint32_t)(r + 1) * 144 + c * 16;
            const char* s = (half ? srcl : srch) + (size_t)r * 128 + c * 16;
            cp16(dst, s);
        }
    } else {
        // zero slots 1..128, both halves, first 128B of each row: 8192 words
        for (int i = 0; i < 32; ++i) {
            int e = tid + i * 256;
            int half = e >= 4096;
            int idx  = half ? e - 4096 : e;
            int r    = idx >> 5, c = idx & 31;
            *(uint32_t*)(sm + xoff + (half ? XLOFF : 0) + (r + 1) * 144 + c * 4) = 0u;
        }
    }
}

__device__ __forceinline__ void issue_w(uint32_t sb_w, int tap, int tid) {
#pragma unroll
    for (int i = 0; i < 4; ++i) {
        int e = tid + i * 256;                      // 0..1023
        int oc = e >> 3, c = e & 7;
        uint32_t dst = sb_w + (uint32_t)oc * 144 + c * 16;
        cp16(dst, (const char*)g_Wh + ((size_t)tap * COUT + oc) * 128 + c * 16);
    }
}

__global__ __launch_bounds__(256, 2)
void conv3x3_mma_kernel() {
    extern __shared__ char sm[];
    const uint32_t sbase = smem_u32(sm);
    const int tid = threadIdx.x;
    const int b   = blockIdx.x >> 7;
    const int y   = blockIdx.x & 127;

    const int wid = tid >> 5, l = tid & 31;
    const int mrow0 = (wid & 1) * 64;       // warp M origin (oc), M=64
    const int ncol0 = (wid >> 1) * 32;      // warp N origin (px), N=32
    const uint32_t frag_off = (uint32_t)(l & 15) * 144 + (uint32_t)(l >> 4) * 16;

    // zero halo slots 0 and 129: 2 buf * 2 half * 2 slot * 32 words = 256 words
    {
        int e = tid;
        int buf  = e >> 7;
        int rem  = e & 127;
        int half = rem >> 6;
        int rem2 = rem & 63;
        int slot = (rem2 >= 32) ? 129 : 0;
        int c    = rem2 & 31;
        *(uint32_t*)(sm + XBUF(buf) + (half ? XLOFF : 0) + slot * 144 + c * 4) = 0u;
    }

    float acc[4][4][4];
#pragma unroll
    for (int mt = 0; mt < 4; ++mt)
#pragma unroll
        for (int nt = 0; nt < 4; ++nt)
#pragma unroll
            for (int j = 0; j < 4; ++j) acc[mt][nt][j] = 0.f;

    issue_xrow(sbase + XBUF(0), sm, XBUF(0), b, y - 1, tid);
    issue_w(sbase + WBUF(0), 0, tid);
    CP_COMMIT();
    issue_xrow(sbase + XBUF(1), sm, XBUF(1), b, y, tid);
    issue_w(sbase + WBUF(1), 1, tid);
    CP_COMMIT();

    for (int t = 0; t < 9; ++t) {
        const int ky = (t >= 6) ? 2 : (t >= 3 ? 1 : 0);
        const int kx = t - 3 * ky;
        CP_WAIT1();
        __syncthreads();

        const uint32_t xb = sbase + XBUF(ky & 1);
        const uint32_t aB = sbase + WBUF(t & 1) + (uint32_t)mrow0 * 144 + frag_off;
        const uint32_t bH = xb + (uint32_t)(kx + ncol0) * 144 + frag_off;
        const uint32_t bL = bH + XLOFF;

#pragma unroll
        for (int kk = 0; kk < 4; ++kk) {
            uint32_t a[16];
#pragma unroll
            for (int mtt = 0; mtt < 4; ++mtt)
                ldmx4(aB + (uint32_t)mtt * 16 * 144 + kk * 32,
                      a[mtt * 4 + 0], a[mtt * 4 + 1], a[mtt * 4 + 2], a[mtt * 4 + 3]);
            // term 1: Wh * Xh
            {
                uint32_t bf[4][2];
#pragma unroll
                for (int nb = 0; nb < 2; ++nb) {
                    uint32_t r0, r1, r2, r3;
                    ldmx4(bH + (uint32_t)nb * 16 * 144 + kk * 32, r0, r1, r2, r3);
                    bf[nb * 2 + 0][0] = r0; bf[nb * 2 + 0][1] = r2;
                    bf[nb * 2 + 1][0] = r1; bf[nb * 2 + 1][1] = r3;
                }
#pragma unroll
                for (int mt = 0; mt < 4; ++mt)
#pragma unroll
                    for (int nt = 0; nt < 4; ++nt)
                        mma16816(acc[mt][nt], a + mt * 4, bf[nt][0], bf[nt][1]);
            }
            // term 2: Wh * Xl
            {
                uint32_t bf[4][2];
#pragma unroll
                for (int nb = 0; nb < 2; ++nb) {
                    uint32_t r0, r1, r2, r3;
                    ldmx4(bL + (uint32_t)nb * 16 * 144 + kk * 32, r0, r1, r2, r3);
                    bf[nb * 2 + 0][0] = r0; bf[nb * 2 + 0][1] = r2;
                    bf[nb * 2 + 1][0] = r1; bf[nb * 2 + 1][1] = r3;
                }
#pragma unroll
                for (int mt = 0; mt < 4; ++mt)
#pragma unroll
                    for (int nt = 0; nt < 4; ++nt)
                        mma16816(acc[mt][nt], a + mt * 4, bf[nt][0], bf[nt][1]);
            }
        }
        __syncthreads();
        if (t < 8) {
            if (t + 2 <= 8) issue_w(sbase + WBUF(t & 1), t + 2, tid);
            if (t == 3)     issue_xrow(sbase + XBUF(0), sm, XBUF(0), b, y + 1, tid);
            CP_COMMIT();
        }
    }

    // epilogue
    float* yb = g_y + (size_t)b * COUT * H_ * W_;
#pragma unroll
    for (int mt = 0; mt < 4; ++mt) {
#pragma unroll
        for (int nt = 0; nt < 4; ++nt) {
            int r   = mrow0 + mt * 16 + (l >> 2);
            int col = ncol0 + nt * 8 + (l & 3) * 2;
            *(float2*)&yb[((size_t)r * H_ + y) * W_ + col]
                = make_float2(acc[mt][nt][0], acc[mt][nt][1]);
            *(float2*)&yb[((size_t)(r + 8) * H_ + y) * W_ + col]
                = make_float2(acc[mt][nt][2], acc[mt][nt][3]);
        }
    }
}

// ---------------- Stage 2: depthwise 4x4 + bias + silu (register blocked) ----
__global__ __launch_bounds__(256)
void dwconv_kernel(const float* __restrict__ Wc, const float* __restrict__ bc) {
    __shared__ float Xs[35][37];
    __shared__ float ws_s[16];
    __shared__ float bias_s;

    const int tid  = threadIdx.x;
    const int tile = blockIdx.x;
    const int c    = blockIdx.y;
    const int b    = blockIdx.z;
    const int i0   = (tile / 5) * 32;
    const int j0   = (tile % 5) * 32;

    const float* yb = g_y + ((size_t)b * COUT + c) * H_ * W_;

    for (int idx = tid; idx < 35 * 35; idx += 256) {
        int rr = idx / 35, cc = idx - rr * 35;
        int gr = i0 - 3 + rr, gc = j0 - 3 + cc;
        float v = 0.f;
        if ((unsigned)gr < H_ && (unsigned)gc < W_) v = yb[gr * W_ + gc];
        Xs[rr][cc] = v;
    }
    if (tid < 16)  ws_s[tid] = Wc[c * 16 + tid];
    if (tid == 16) bias_s    = bc[c];
    __syncthreads();

    float w[16];
#pragma unroll
    for (int i = 0; i < 16; ++i) w[i] = ws_s[i];
    const float bias = bias_s;

    const int oy  = tid >> 3;          // 0..31
    const int ox4 = (tid & 7) * 4;     // 0..28

    float a0 = bias, a1 = bias, a2 = bias, a3 = bias;
#pragma unroll
    for (int ky = 0; ky < 4; ++ky) {
        const float* xr = &Xs[oy + ky][ox4];
        float x0 = xr[0], x1 = xr[1], x2 = xr[2], x3 = xr[3],
              x4 = xr[4], x5 = xr[5], x6 = xr[6];
        const float* wk = w + ky * 4;
        a0 += x0 * wk[0] + x1 * wk[1] + x2 * wk[2] + x3 * wk[3];
        a1 += x1 * wk[0] + x2 * wk[1] + x3 * wk[2] + x4 * wk[3];
        a2 += x2 * wk[0] + x3 * wk[1] + x4 * wk[2] + x5 * wk[3];
        a3 += x3 * wk[0] + x4 * wk[1] + x5 * wk[2] + x6 * wk[3];
    }

    const int gi = i0 + oy;
    if (gi < HO) {
        float* ob = g_xh + ((size_t)b * COUT + c) * HO * WO + (size_t)gi * WO + j0 + ox4;
        float r0 = a0 / (1.f + __expf(-a0));
        float r1 = a1 / (1.f + __expf(-a1));
        float r2 = a2 / (1.f + __expf(-a2));
        float r3 = a3 / (1.f + __expf(-a3));
        int gj = j0 + ox4;
        if (gj + 3 < WO) {
            ob[0] = r0; ob[1] = r1; ob[2] = r2; ob[3] = r3;
        } else {
            if (gj + 0 < WO) ob[0] = r0;
            if (gj + 1 < WO) ob[1] = r1;
            if (gj + 2 < WO) ob[2] = r2;
            if (gj + 3 < WO) ob[3] = r3;
        }
    }
}

// ---------------- Stage 3: head matmul ----------------
#define GG 549152
__global__ __launch_bounds__(256, 4)
void headmm_kernel(const float* __restrict__ W_out, float* __restrict__ out) {
    __shared__ float Vs[2048];
    const int tid = threadIdx.x;
    const int e   = tid & 31;
    const int wp  = tid >> 5;

    float wrow[32];
#pragma unroll
    for (int d = 0; d < 32; ++d) wrow[d] = W_out[e * 32 + d];

    const int nchunks = (GG + 63) / 64;
    for (int ch = blockIdx.x; ch < nchunks; ch += gridDim.x) {
        size_t base  = (size_t)ch * 2048;
        int    nelem = min(2048, (int)((size_t)GG * 32 - base));
        int    nvec  = nelem >> 2;
        for (int idx = tid; idx < nvec; idx += 256)
            *(float4*)&Vs[idx * 4] = *(const float4*)(g_xh + base + (size_t)idx * 4);
        __syncthreads();
        int ng = nelem >> 5;
#pragma unroll
        for (int k = 0; k < 8; ++k) {
            int gl = wp + k * 8;
            if (gl < ng) {
                const float* v = &Vs[gl * 32];
                float a = 0.f;
#pragma unroll
                for (int d = 0; d < 32; ++d) a += wrow[d] * v[d];
                out[base + (size_t)gl * 32 + e] = a;
            }
        }
        __syncthreads();
    }
}

// ---------------- launch ----------------
extern "C" void kernel_launch(void* const* d_in, const int* in_sizes, int n_in,
                              void* d_out, int out_size) {
    const float* x      = (const float*)d_in[0];
    const float* W_in   = (const float*)d_in[1];
    const float* W_conv = (const float*)d_in[2];
    const float* b_conv = (const float*)d_in[3];
    const float* W_out  = (const float*)d_in[7];
    float* out = (float*)d_out;

    cudaFuncSetAttribute(conv3x3_mma_kernel,
                         cudaFuncAttributeMaxDynamicSharedMemorySize, SM_TOTAL);

    prep_w_kernel<<<9, 128>>>(W_in);
    prep_x_kernel<<<dim3(H_, B_), 256>>>(x);
    conv3x3_mma_kernel<<<B_ * H_, 256, SM_TOTAL>>>();
    dwconv_kernel<<<dim3(25, 128, 8), 256>>>(W_conv, b_conv);
    headmm_kernel<<<8581, 256>>>(W_out, out);
}

// round 7
// speedup vs baseline: 3.1940x; 1.0862x over previous
#include <cuda_runtime.h>
#include <cuda_fp16.h>
#include <cstdint>

#define B_    8
#define CIN   64
#define H_    128
#define W_    128
#define COUT  128
#define HO    131
#define WO    131

// ---------------- device scratch ----------------
__device__ __align__(16) float   g_y [B_ * COUT * H_ * W_];
__device__ __align__(16) float   g_xh[B_ * COUT * HO * WO];
__device__ __align__(16) __half  g_Xh[B_ * H_ * W_ * CIN];   // NHWC fp16
__device__ __align__(16) __half  g_Wh[9 * COUT * CIN];       // [tap][oc][ic] fp16

// ---------------- helpers ----------------
__device__ __forceinline__ uint32_t smem_u32(const void* p) {
    uint32_t a;
    asm("{ .reg .u64 t; cvta.to.shared.u64 t, %1; cvt.u32.u64 %0, t; }" : "=r"(a) : "l"(p));
    return a;
}
__device__ __forceinline__ void cp16(uint32_t dst, const void* src) {
    asm volatile("cp.async.cg.shared.global [%0], [%1], 16;" :: "r"(dst), "l"(src));
}
#define CP_COMMIT() asm volatile("cp.async.commit_group;" ::: "memory")
#define CP_WAIT1()  asm volatile("cp.async.wait_group 1;" ::: "memory")

__device__ __forceinline__ void ldmx4(uint32_t addr, uint32_t& r0, uint32_t& r1,
                                      uint32_t& r2, uint32_t& r3) {
    asm volatile("ldmatrix.sync.aligned.m8n8.x4.shared.b16 {%0,%1,%2,%3}, [%4];"
                 : "=r"(r0), "=r"(r1), "=r"(r2), "=r"(r3) : "r"(addr));
}
__device__ __forceinline__ void mma16816(float* c, const uint32_t* a, uint32_t b0, uint32_t b1) {
    asm volatile(
        "mma.sync.aligned.m16n8k16.row.col.f32.f16.f16.f32 "
        "{%0,%1,%2,%3}, {%4,%5,%6,%7}, {%8,%9}, {%0,%1,%2,%3};"
        : "+f"(c[0]), "+f"(c[1]), "+f"(c[2]), "+f"(c[3])
        : "r"(a[0]), "r"(a[1]), "r"(a[2]), "r"(a[3]), "r"(b0), "r"(b1));
}

// ---------------- SMEM layout (bytes) ----------------
// X buffers: 2 x [132 slots x 144B]  (slot = px+1, px in -1..130)
// W buffers: 2 x [128 x 144B]
#define XBUF(b)   ((b) * 19008)
#define WBUF(b)   (38016 + (b) * 18432)
#define SM_TOTAL  74880

// ---------------- prep kernels ----------------
__global__ void prep_w_kernel(const float* __restrict__ W_in) {
    int tap = blockIdx.x;      // 0..8
    int oc  = threadIdx.x;     // 0..127
    for (int ic = 0; ic < CIN; ++ic) {
        float v = W_in[(size_t)((128 + oc) * CIN + ic) * 9 + tap];
        g_Wh[(tap * COUT + oc) * CIN + ic] = __float2half(v);
    }
}

__global__ __launch_bounds__(256) void prep_x_kernel(const float* __restrict__ x) {
    __shared__ float s[W_ * (CIN + 1)];
    int y = blockIdx.x, b = blockIdx.y, tid = threadIdx.x;
    for (int k = 0; k < 32; ++k) {
        int idx = tid + k * 256;
        int ic = idx >> 7, xx = idx & 127;
        s[xx * (CIN + 1) + ic] = x[((size_t)(b * CIN + ic) * H_ + y) * W_ + xx];
    }
    __syncthreads();
    size_t obase = ((size_t)(b * H_ + y) * W_) * CIN;
    for (int k = 0; k < 32; ++k) {
        int idx = tid + k * 256;
        int p = idx >> 6, ic = idx & 63;
        g_Xh[obase + (size_t)p * CIN + ic] = __float2half(s[p * (CIN + 1) + ic]);
    }
}

// ---------------- Stage 1: implicit-GEMM conv3x3, fp16 single-term ----------------
__device__ __forceinline__ void issue_xrow(uint32_t sb_x, char* sm, int xoff,
                                           int b, int row, int tid) {
    if ((unsigned)row < (unsigned)H_) {
        const char* src = (const char*)g_Xh + ((size_t)(b * H_ + row) * W_) * CIN * 2;
#pragma unroll
        for (int i = 0; i < 4; ++i) {
            int e = tid + i * 256;                  // 0..1023
            int r = e >> 3, c = e & 7;
            cp16(sb_x + (uint32_t)(r + 1) * 144 + c * 16, src + (size_t)r * 128 + c * 16);
        }
    } else {
        // zero slots 1..128, first 128B of each row: 4096 words over 256 threads
        for (int i = 0; i < 16; ++i) {
            int e = tid + i * 256;
            int r = e >> 5, c = e & 31;
            *(uint32_t*)(sm + xoff + (r + 1) * 144 + c * 4) = 0u;
        }
    }
}

__device__ __forceinline__ void issue_w(uint32_t sb_w, int tap, int tid) {
#pragma unroll
    for (int i = 0; i < 4; ++i) {
        int e = tid + i * 256;                      // 0..1023
        int oc = e >> 3, c = e & 7;
        cp16(sb_w + (uint32_t)oc * 144 + c * 16,
             (const char*)g_Wh + ((size_t)tap * COUT + oc) * 128 + c * 16);
    }
}

__global__ __launch_bounds__(256, 2)
void conv3x3_mma_kernel() {
    extern __shared__ char sm[];
    const uint32_t sbase = smem_u32(sm);
    const int tid = threadIdx.x;
    const int b   = blockIdx.x >> 7;
    const int y   = blockIdx.x & 127;

    const int wid = tid >> 5, l = tid & 31;
    const int mrow0 = (wid & 1) * 64;       // warp M origin (oc), M=64
    const int ncol0 = (wid >> 1) * 32;      // warp N origin (px), N=32
    const uint32_t frag_off = (uint32_t)(l & 15) * 144 + (uint32_t)(l >> 4) * 16;

    // zero halo slots 0 and 129: 2 buf * 2 slot * 32 words = 128 words
    if (tid < 128) {
        int buf  = tid >> 6;
        int rem  = tid & 63;
        int slot = (rem >= 32) ? 129 : 0;
        int c    = rem & 31;
        *(uint32_t*)(sm + XBUF(buf) + slot * 144 + c * 4) = 0u;
    }

    float acc[4][4][4];
#pragma unroll
    for (int mt = 0; mt < 4; ++mt)
#pragma unroll
        for (int nt = 0; nt < 4; ++nt)
#pragma unroll
            for (int j = 0; j < 4; ++j) acc[mt][nt][j] = 0.f;

    issue_xrow(sbase + XBUF(0), sm, XBUF(0), b, y - 1, tid);
    issue_w(sbase + WBUF(0), 0, tid);
    CP_COMMIT();
    issue_xrow(sbase + XBUF(1), sm, XBUF(1), b, y, tid);
    issue_w(sbase + WBUF(1), 1, tid);
    CP_COMMIT();

    for (int t = 0; t < 9; ++t) {
        const int ky = (t >= 6) ? 2 : (t >= 3 ? 1 : 0);
        const int kx = t - 3 * ky;
        CP_WAIT1();
        __syncthreads();

        const uint32_t aB = sbase + WBUF(t & 1) + (uint32_t)mrow0 * 144 + frag_off;
        const uint32_t bB = sbase + XBUF(ky & 1) + (uint32_t)(kx + ncol0) * 144 + frag_off;

#pragma unroll
        for (int kk = 0; kk < 4; ++kk) {
            uint32_t a[16];
#pragma unroll
            for (int mtt = 0; mtt < 4; ++mtt)
                ldmx4(aB + (uint32_t)mtt * 16 * 144 + kk * 32,
                      a[mtt * 4 + 0], a[mtt * 4 + 1], a[mtt * 4 + 2], a[mtt * 4 + 3]);
            uint32_t bf[4][2];
#pragma unroll
            for (int nb = 0; nb < 2; ++nb) {
                uint32_t r0, r1, r2, r3;
                ldmx4(bB + (uint32_t)nb * 16 * 144 + kk * 32, r0, r1, r2, r3);
                bf[nb * 2 + 0][0] = r0; bf[nb * 2 + 0][1] = r2;
                bf[nb * 2 + 1][0] = r1; bf[nb * 2 + 1][1] = r3;
            }
#pragma unroll
            for (int mt = 0; mt < 4; ++mt)
#pragma unroll
                for (int nt = 0; nt < 4; ++nt)
                    mma16816(acc[mt][nt], a + mt * 4, bf[nt][0], bf[nt][1]);
        }
        __syncthreads();
        if (t < 8) {
            if (t + 2 <= 8) issue_w(sbase + WBUF(t & 1), t + 2, tid);
            if (t == 3)     issue_xrow(sbase + XBUF(0), sm, XBUF(0), b, y + 1, tid);
            CP_COMMIT();
        }
    }

    // epilogue
    float* yb = g_y + (size_t)b * COUT * H_ * W_;
#pragma unroll
    for (int mt = 0; mt < 4; ++mt) {
#pragma unroll
        for (int nt = 0; nt < 4; ++nt) {
            int r   = mrow0 + mt * 16 + (l >> 2);
            int col = ncol0 + nt * 8 + (l & 3) * 2;
            *(float2*)&yb[((size_t)r * H_ + y) * W_ + col]
                = make_float2(acc[mt][nt][0], acc[mt][nt][1]);
            *(float2*)&yb[((size_t)(r + 8) * H_ + y) * W_ + col]
                = make_float2(acc[mt][nt][2], acc[mt][nt][3]);
        }
    }
}

// ---------------- Stage 2: depthwise 4x4 + bias + silu (register blocked) ----
__global__ __launch_bounds__(256)
void dwconv_kernel(const float* __restrict__ Wc, const float* __restrict__ bc) {
    __shared__ float Xs[35][37];
    __shared__ float ws_s[16];
    __shared__ float bias_s;

    const int tid  = threadIdx.x;
    const int tile = blockIdx.x;
    const int c    = blockIdx.y;
    const int b    = blockIdx.z;
    const int i0   = (tile / 5) * 32;
    const int j0   = (tile % 5) * 32;

    const float* yb = g_y + ((size_t)b * COUT + c) * H_ * W_;

    for (int idx = tid; idx < 35 * 35; idx += 256) {
        int rr = idx / 35, cc = idx - rr * 35;
        int gr = i0 - 3 + rr, gc = j0 - 3 + cc;
        float v = 0.f;
        if ((unsigned)gr < H_ && (unsigned)gc < W_) v = yb[gr * W_ + gc];
        Xs[rr][cc] = v;
    }
    if (tid < 16)  ws_s[tid] = Wc[c * 16 + tid];
    if (tid == 16) bias_s    = bc[c];
    __syncthreads();

    float w[16];
#pragma unroll
    for (int i = 0; i < 16; ++i) w[i] = ws_s[i];
    const float bias = bias_s;

    const int oy  = tid >> 3;          // 0..31
    const int ox4 = (tid & 7) * 4;     // 0..28

    float a0 = bias, a1 = bias, a2 = bias, a3 = bias;
#pragma unroll
    for (int ky = 0; ky < 4; ++ky) {
        const float* xr = &Xs[oy + ky][ox4];
        float x0 = xr[0], x1 = xr[1], x2 = xr[2], x3 = xr[3],
              x4 = xr[4], x5 = xr[5], x6 = xr[6];
        const float* wk = w + ky * 4;
        a0 += x0 * wk[0] + x1 * wk[1] + x2 * wk[2] + x3 * wk[3];
        a1 += x1 * wk[0] + x2 * wk[1] + x3 * wk[2] + x4 * wk[3];
        a2 += x2 * wk[0] + x3 * wk[1] + x4 * wk[2] + x5 * wk[3];
        a3 += x3 * wk[0] + x4 * wk[1] + x5 * wk[2] + x6 * wk[3];
    }

    const int gi = i0 + oy;
    if (gi < HO) {
        float* ob = g_xh + ((size_t)b * COUT + c) * HO * WO + (size_t)gi * WO + j0 + ox4;
        float r0 = a0 / (1.f + __expf(-a0));
        float r1 = a1 / (1.f + __expf(-a1));
        float r2 = a2 / (1.f + __expf(-a2));
        float r3 = a3 / (1.f + __expf(-a3));
        int gj = j0 + ox4;
        if (gj + 3 < WO) {
            ob[0] = r0; ob[1] = r1; ob[2] = r2; ob[3] = r3;
        } else {
            if (gj + 0 < WO) ob[0] = r0;
            if (gj + 1 < WO) ob[1] = r1;
            if (gj + 2 < WO) ob[2] = r2;
            if (gj + 3 < WO) ob[3] = r3;
        }
    }
}

// ---------------- Stage 3: head matmul ----------------
#define GG 549152
__global__ __launch_bounds__(256, 4)
void headmm_kernel(const float* __restrict__ W_out, float* __restrict__ out) {
    __shared__ float Vs[2048];
    const int tid = threadIdx.x;
    const int e   = tid & 31;
    const int wp  = tid >> 5;

    float wrow[32];
#pragma unroll
    for (int d = 0; d < 32; ++d) wrow[d] = W_out[e * 32 + d];

    const int nchunks = (GG + 63) / 64;
    for (int ch = blockIdx.x; ch < nchunks; ch += gridDim.x) {
        size_t base  = (size_t)ch * 2048;
        int    nelem = min(2048, (int)((size_t)GG * 32 - base));
        int    nvec  = nelem >> 2;
        for (int idx = tid; idx < nvec; idx += 256)
            *(float4*)&Vs[idx * 4] = *(const float4*)(g_xh + base + (size_t)idx * 4);
        __syncthreads();
        int ng = nelem >> 5;
#pragma unroll
        for (int k = 0; k < 8; ++k) {
            int gl = wp + k * 8;
            if (gl < ng) {
                const float* v = &Vs[gl * 32];
                float a = 0.f;
#pragma unroll
                for (int d = 0; d < 32; ++d) a += wrow[d] * v[d];
                out[base + (size_t)gl * 32 + e] = a;
            }
        }
        __syncthreads();
    }
}

// ---------------- launch ----------------
extern "C" void kernel_launch(void* const* d_in, const int* in_sizes, int n_in,
                              void* d_out, int out_size) {
    const float* x      = (const float*)d_in[0];
    const float* W_in   = (const float*)d_in[1];
    const float* W_conv = (const float*)d_in[2];
    const float* b_conv = (const float*)d_in[3];
    const float* W_out  = (const float*)d_in[7];
    float* out = (float*)d_out;

    cudaFuncSetAttribute(conv3x3_mma_kernel,
                         cudaFuncAttributeMaxDynamicSharedMemorySize, SM_TOTAL);

    prep_w_kernel<<<9, 128>>>(W_in);
    prep_x_kernel<<<dim3(H_, B_), 256>>>(x);
    conv3x3_mma_kernel<<<B_ * H_, 256, SM_TOTAL>>>();
    dwconv_kernel<<<dim3(25, 128, 8), 256>>>(W_conv, b_conv);
    headmm_kernel<<<8581, 256>>>(W_out, out);
}